// round 13
// baseline (speedup 1.0000x reference)
#include <cuda_runtime.h>
#include <cuda_bf16.h>
#include <cuda_fp8.h>
#include <math.h>
#include <stdint.h>

#define VOCAB1 32001
#define DIN 512
#define DR  512
#define DF  2048
#define BB  64
#define TT  20
#define G4  2048
#define NBLK_LG 251

// ================= device scratch =================
__device__ __align__(16) __nv_bfloat16 g_xsb[TT * BB * DIN];
__device__ __align__(16) float g_gx[(size_t)TT * BB * G4];
__device__ __align__(16) float g_c[BB * DR];
__device__ __align__(16) __nv_bfloat16 g_hb[BB * DR];
__device__ __align__(16) unsigned char g_hs8[TT * BB * DR];
__device__ __align__(16) unsigned char g_wl8[(size_t)VOCAB1 * DR];
__device__ __align__(16) __nv_bfloat16 g_wib[(size_t)G4 * DIN];
__device__ __align__(16) __nv_bfloat16 g_whb[(size_t)G4 * DR];
__device__ __align__(16) float g_bias2[G4];
__device__ __align__(16) float g_lse[BB * TT];
__device__ __align__(16) float g_x0p[8 * BB * DIN];
__device__ __align__(16) float g_pmax[BB * TT * NBLK_LG];
__device__ __align__(16) float g_psum[BB * TT * NBLK_LG];
__device__ int g_cnt;

// ================= fused init + embedding gather =================
__global__ void init_gather(const int* __restrict__ seq, const float* __restrict__ embed,
                            const float* __restrict__ b_ih, const float* __restrict__ b_hh) {
    int bid = blockIdx.x, tid = threadIdx.x;
    int id = bid * 128 + tid;
    if (id < BB * DR) g_c[id] = 0.f;
    if (id < G4) g_bias2[id] = b_ih[id] + b_hh[id];
    if (id == 0) g_cnt = 0;

    int t = 1 + (bid >> 6), b = bid & 63;
    int idx = seq[b * TT + t];
    if (idx < 0) idx = 0;
    if (idx > VOCAB1 - 1) idx = VOCAB1 - 1;
    float4 v = reinterpret_cast<const float4*>(embed + (size_t)idx * DIN)[tid];
    __nv_bfloat162 p0 = __floats2bfloat162_rn(v.x, v.y);
    __nv_bfloat162 p1 = __floats2bfloat162_rn(v.z, v.w);
    uint2 u;
    u.x = *reinterpret_cast<uint32_t*>(&p0);
    u.y = *reinterpret_cast<uint32_t*>(&p1);
    reinterpret_cast<uint2*>(g_xsb + ((size_t)t * BB + b) * DIN)[tid] = u;
}

// ================= fused weight conversion =================
#define NQ_WL ((size_t)VOCAB1 * DR / 4)
#define NQ_WI ((size_t)G4 * DIN / 4)
#define NQ_WH ((size_t)G4 * DR / 4)
__global__ void conv_all(const float* __restrict__ wl, const float* __restrict__ wi,
                         const float* __restrict__ wh) {
    size_t q = (size_t)blockIdx.x * blockDim.x + threadIdx.x;
    if (q < NQ_WL) {
        size_t i = q * 4;
        float4 v = *reinterpret_cast<const float4*>(wl + i);
        uint32_t r =
            (uint32_t)__nv_cvt_float_to_fp8(v.x * 64.f, __NV_SATFINITE, __NV_E4M3)
          | ((uint32_t)__nv_cvt_float_to_fp8(v.y * 64.f, __NV_SATFINITE, __NV_E4M3) << 8)
          | ((uint32_t)__nv_cvt_float_to_fp8(v.z * 64.f, __NV_SATFINITE, __NV_E4M3) << 16)
          | ((uint32_t)__nv_cvt_float_to_fp8(v.w * 64.f, __NV_SATFINITE, __NV_E4M3) << 24);
        *reinterpret_cast<uint32_t*>(g_wl8 + i) = r;
        return;
    }
    q -= NQ_WL;
    const float* src;
    __nv_bfloat16* dst;
    if (q < NQ_WI) { src = wi; dst = g_wib; }
    else if (q < NQ_WI + NQ_WH) { q -= NQ_WI; src = wh; dst = g_whb; }
    else return;
    size_t i = q * 4;
    float4 v = *reinterpret_cast<const float4*>(src + i);
    __nv_bfloat162 p0 = __floats2bfloat162_rn(v.x, v.y);
    __nv_bfloat162 p1 = __floats2bfloat162_rn(v.z, v.w);
    uint2 u;
    u.x = *reinterpret_cast<uint32_t*>(&p0);
    u.y = *reinterpret_cast<uint32_t*>(&p1);
    *reinterpret_cast<uint2*>(&dst[i]) = u;
}
#define CONV_BLOCKS ((int)((NQ_WL + NQ_WI + NQ_WH + 255) / 256))

// ================= x0: k-split fp32 GEMM =================
__global__ void x0_ksplit(const float* __restrict__ A, const float* __restrict__ Bm) {
    __shared__ float As[16][64];
    __shared__ float Bs[16][64];
    const int tid = threadIdx.x;
    const int n0 = blockIdx.x * 64;
    const int kbeg = blockIdx.y * 256;
    const int tx = tid & 15, ty = tid >> 4;
    float acc[4][4] = {};
    for (int kt = 0; kt < 256; kt += 16) {
        {
            int row = tid >> 2, kq = (tid & 3) << 2;
            float4 v = *reinterpret_cast<const float4*>(A + (size_t)row * DF + kbeg + kt + kq);
            As[kq + 0][row] = v.x; As[kq + 1][row] = v.y;
            As[kq + 2][row] = v.z; As[kq + 3][row] = v.w;
        }
        {
            int row = tid >> 2, kq = (tid & 3) << 2;
            float4 v = *reinterpret_cast<const float4*>(Bm + (size_t)(n0 + row) * DF + kbeg + kt + kq);
            Bs[kq + 0][row] = v.x; Bs[kq + 1][row] = v.y;
            Bs[kq + 2][row] = v.z; Bs[kq + 3][row] = v.w;
        }
        __syncthreads();
#pragma unroll
        for (int k = 0; k < 16; k++) {
            float a[4], b[4];
#pragma unroll
            for (int i = 0; i < 4; i++) a[i] = As[k][ty * 4 + i];
#pragma unroll
            for (int j = 0; j < 4; j++) b[j] = Bs[k][tx * 4 + j];
#pragma unroll
            for (int i = 0; i < 4; i++)
#pragma unroll
                for (int j = 0; j < 4; j++) acc[i][j] = fmaf(a[i], b[j], acc[i][j]);
        }
        __syncthreads();
    }
    float* p = g_x0p + (size_t)blockIdx.y * BB * DIN;
#pragma unroll
    for (int i = 0; i < 4; i++)
#pragma unroll
        for (int j = 0; j < 4; j++)
            p[(ty * 4 + i) * DIN + n0 + tx * 4 + j] = acc[i][j];
}

__global__ void x0_reduce(const float* __restrict__ b_img) {
    int id = blockIdx.x * blockDim.x + threadIdx.x;
    float s = b_img[id & 511];
#pragma unroll
    for (int kb = 0; kb < 8; kb++) s += g_x0p[kb * BB * DIN + id];
    g_xsb[id] = __float2bfloat16(s);
}

// ================= mma primitives =================
__device__ __forceinline__ void mma16816(float* d, uint32_t a0, uint32_t a1,
                                         uint32_t a2, uint32_t a3,
                                         uint32_t b0, uint32_t b1) {
    asm volatile(
        "mma.sync.aligned.m16n8k16.row.col.f32.bf16.bf16.f32 "
        "{%0,%1,%2,%3}, {%4,%5,%6,%7}, {%8,%9}, {%0,%1,%2,%3};"
        : "+f"(d[0]), "+f"(d[1]), "+f"(d[2]), "+f"(d[3])
        : "r"(a0), "r"(a1), "r"(a2), "r"(a3), "r"(b0), "r"(b1));
}

__device__ __forceinline__ void mma_fp8(float* d, uint32_t a0, uint32_t a1,
                                        uint32_t a2, uint32_t a3,
                                        uint32_t b0, uint32_t b1) {
    asm volatile(
        "mma.sync.aligned.m16n8k32.row.col.f32.e4m3.e4m3.f32 "
        "{%0,%1,%2,%3}, {%4,%5,%6,%7}, {%8,%9}, {%0,%1,%2,%3};"
        : "+f"(d[0]), "+f"(d[1]), "+f"(d[2]), "+f"(d[3])
        : "r"(a0), "r"(a1), "r"(a2), "r"(a3), "r"(b0), "r"(b1));
}

__device__ __forceinline__ float sigmoidf_(float x) { return 1.f / (1.f + __expf(-x)); }

__device__ __forceinline__ uint4 ldcg_v4(const uint4* p) {
    uint4 v;
    asm volatile("ld.global.cg.v4.u32 {%0,%1,%2,%3}, [%4];"
                 : "=r"(v.x), "=r"(v.y), "=r"(v.z), "=r"(v.w) : "l"(p));
    return v;
}

// ================= persistent LSTM (64 CTAs, single launch) =================
#define HSTR 520
#define ST_SMEM (64 * HSTR * 2 + 32 * HSTR * 2 + 64 * 33 * 4)

__global__ void __launch_bounds__(256) lstm_persist64() {
    extern __shared__ char smem[];
    __nv_bfloat16* hS = reinterpret_cast<__nv_bfloat16*>(smem);
    __nv_bfloat16* wS = reinterpret_cast<__nv_bfloat16*>(smem + 64 * HSTR * 2);
    float* gS = reinterpret_cast<float*>(smem + 64 * HSTR * 2 + 32 * HSTR * 2);
    const int tid = threadIdx.x, wid = tid >> 5, lid = tid & 31;
    const int gid = lid >> 2, tig = lid & 3;
    const int cta = blockIdx.x;
    const int c0 = cta * 8;

    for (int q = tid; q < 2048; q += 256) {
        int j = q >> 6, g = q & 63;
        int wr = (j >> 3) * 512 + c0 + (j & 7);
        *reinterpret_cast<uint4*>(wS + j * HSTR + g * 8) =
            reinterpret_cast<const uint4*>(g_whb + (size_t)wr * DR)[g];
    }
    __syncthreads();

    const int mrow = (wid >> 1) * 16;
    const int ncol = (wid & 1) * 16;

    for (int t = 0; t < TT; t++) {
        if (t > 0) {
            if (tid == 0) {
                int target = 64 * t, v;
                long guard = 0;
                do {
                    asm volatile("ld.global.cg.s32 %0, [%1];" : "=r"(v) : "l"(&g_cnt));
                } while (v < target && ++guard < (1L << 31));
            }
            __syncthreads();
            {
                const uint4* src = reinterpret_cast<const uint4*>(g_hb);
                for (int q = tid; q < 4096; q += 256) {
                    int row = q >> 6, g = q & 63;
                    *reinterpret_cast<uint4*>(hS + row * HSTR + g * 8) = ldcg_v4(src + row * 64 + g);
                }
            }
            __syncthreads();
            float acc[2][4] = {};
#pragma unroll 4
            for (int ks = 0; ks < 512; ks += 16) {
                const __nv_bfloat16* ap = hS + (mrow + gid) * HSTR + ks + tig * 2;
                uint32_t a0 = *reinterpret_cast<const uint32_t*>(ap);
                uint32_t a1 = *reinterpret_cast<const uint32_t*>(ap + 8 * HSTR);
                uint32_t a2 = *reinterpret_cast<const uint32_t*>(ap + 8);
                uint32_t a3 = *reinterpret_cast<const uint32_t*>(ap + 8 * HSTR + 8);
#pragma unroll
                for (int nt = 0; nt < 2; nt++) {
                    const __nv_bfloat16* bp = wS + (ncol + nt * 8 + gid) * HSTR + ks + tig * 2;
                    uint32_t b0 = *reinterpret_cast<const uint32_t*>(bp);
                    uint32_t b1 = *reinterpret_cast<const uint32_t*>(bp + 8);
                    mma16816(acc[nt], a0, a1, a2, a3, b0, b1);
                }
            }
#pragma unroll
            for (int nt = 0; nt < 2; nt++) {
                int r0 = mrow + gid;
                int c = ncol + nt * 8 + tig * 2;
                gS[r0 * 33 + c]           = acc[nt][0];
                gS[r0 * 33 + c + 1]       = acc[nt][1];
                gS[(r0 + 8) * 33 + c]     = acc[nt][2];
                gS[(r0 + 8) * 33 + c + 1] = acc[nt][3];
            }
            __syncthreads();
        }

#pragma unroll
        for (int e = tid; e < 512; e += 256) {
            int b = e >> 3, jl = e & 7;
            int r = c0 + jl;
            const float* gxp = g_gx + ((size_t)t * BB + b) * G4;
            float gi = gxp[r], gf = gxp[512 + r], gg = gxp[1024 + r], go = gxp[1536 + r];
            if (t > 0) {
                gi += gS[b * 33 + jl];
                gf += gS[b * 33 + 8 + jl];
                gg += gS[b * 33 + 16 + jl];
                go += gS[b * 33 + 24 + jl];
            }
            int id = b * DR + r;
            float c = (t > 0) ? g_c[id] : 0.f;
            float cn = sigmoidf_(gf) * c + sigmoidf_(gi) * tanhf(gg);
            float hn = sigmoidf_(go) * tanhf(cn);
            g_c[id] = cn;
            g_hb[id] = __float2bfloat16(hn);
            g_hs8[(size_t)t * BB * DR + id] =
                __nv_cvt_float_to_fp8(hn * 64.f, __NV_SATFINITE, __NV_E4M3);
        }
        __syncthreads();
        if (tid == 0) {
            __threadfence();
            atomicAdd(&g_cnt, 1);
        }
    }
}

// ================= bf16 mma GEMM (gates_x), K=512 =================
#define SP 40
#define LG_DSMEM (128 * 132 * 4)

__global__ void __launch_bounds__(256) bmma_gates(const __nv_bfloat16* __restrict__ Abm,
                                                  const __nv_bfloat16* __restrict__ Bbm,
                                                  const float* __restrict__ bias,
                                                  float* __restrict__ Cp) {
    extern __shared__ char smem[];
    __nv_bfloat16* Asp = reinterpret_cast<__nv_bfloat16*>(smem);
    __nv_bfloat16* Bsp = reinterpret_cast<__nv_bfloat16*>(smem + 10240);
    const int tid = threadIdx.x, wid = tid >> 5, lid = tid & 31;
    const int gid = lid >> 2, tig = lid & 3;
    const int n0 = blockIdx.x * 128;
    const int m0 = blockIdx.y * 128;
    const int wm = (wid >> 2) * 64;
    const int wn = (wid & 3) * 32;
    const int NT = G4;

    float acc[4][4][4];
#pragma unroll
    for (int i = 0; i < 4; i++)
#pragma unroll
        for (int j = 0; j < 4; j++)
#pragma unroll
            for (int r = 0; r < 4; r++) acc[i][j][r] = 0.f;

    const int li0 = tid * 2, li1 = tid * 2 + 1;
    const int ar0 = li0 >> 2, ag0 = li0 & 3, ar1 = li1 >> 2, ag1 = li1 & 3;

    uint4 pa0, pa1, pb0, pb1;
    pa0 = *reinterpret_cast<const uint4*>(Abm + (size_t)(m0 + ar0) * DIN + ag0 * 8);
    pa1 = *reinterpret_cast<const uint4*>(Abm + (size_t)(m0 + ar1) * DIN + ag1 * 8);
    pb0 = *reinterpret_cast<const uint4*>(Bbm + (size_t)(n0 + ar0) * DIN + ag0 * 8);
    pb1 = *reinterpret_cast<const uint4*>(Bbm + (size_t)(n0 + ar1) * DIN + ag1 * 8);

    for (int kt = 0; kt < 16; kt++) {
        __syncthreads();
        *reinterpret_cast<uint4*>(Asp + ar0 * SP + ag0 * 8) = pa0;
        *reinterpret_cast<uint4*>(Asp + ar1 * SP + ag1 * 8) = pa1;
        *reinterpret_cast<uint4*>(Bsp + ar0 * SP + ag0 * 8) = pb0;
        *reinterpret_cast<uint4*>(Bsp + ar1 * SP + ag1 * 8) = pb1;
        __syncthreads();
        if (kt < 15) {
            int k0 = (kt + 1) * 32;
            pa0 = *reinterpret_cast<const uint4*>(Abm + (size_t)(m0 + ar0) * DIN + k0 + ag0 * 8);
            pa1 = *reinterpret_cast<const uint4*>(Abm + (size_t)(m0 + ar1) * DIN + k0 + ag1 * 8);
            pb0 = *reinterpret_cast<const uint4*>(Bbm + (size_t)(n0 + ar0) * DIN + k0 + ag0 * 8);
            pb1 = *reinterpret_cast<const uint4*>(Bbm + (size_t)(n0 + ar1) * DIN + k0 + ag1 * 8);
        }
#pragma unroll
        for (int ks = 0; ks < 32; ks += 16) {
            uint32_t af[4][4], bf[4][2];
#pragma unroll
            for (int mt = 0; mt < 4; mt++) {
                int r = wm + mt * 16 + gid;
                int k = ks + tig * 2;
                af[mt][0] = *reinterpret_cast<const uint32_t*>(Asp + r * SP + k);
                af[mt][1] = *reinterpret_cast<const uint32_t*>(Asp + (r + 8) * SP + k);
                af[mt][2] = *reinterpret_cast<const uint32_t*>(Asp + r * SP + k + 8);
                af[mt][3] = *reinterpret_cast<const uint32_t*>(Asp + (r + 8) * SP + k + 8);
            }
#pragma unroll
            for (int nt = 0; nt < 4; nt++) {
                int n = wn + nt * 8 + gid;
                int k = ks + tig * 2;
                bf[nt][0] = *reinterpret_cast<const uint32_t*>(Bsp + n * SP + k);
                bf[nt][1] = *reinterpret_cast<const uint32_t*>(Bsp + n * SP + k + 8);
            }
#pragma unroll
            for (int mt = 0; mt < 4; mt++)
#pragma unroll
                for (int nt = 0; nt < 4; nt++)
                    mma16816(acc[mt][nt], af[mt][0], af[mt][1], af[mt][2], af[mt][3],
                             bf[nt][0], bf[nt][1]);
        }
    }

    __syncthreads();
    float* stg = reinterpret_cast<float*>(smem);
#pragma unroll
    for (int mt = 0; mt < 4; mt++) {
#pragma unroll
        for (int nt = 0; nt < 4; nt++) {
            int r = wm + mt * 16 + gid;
            int c = wn + nt * 8 + tig * 2;
            int n = n0 + c;
            float bv0 = bias[n], bv1 = bias[n + 1];
            stg[r * 132 + c]           = acc[mt][nt][0] + bv0;
            stg[r * 132 + c + 1]       = acc[mt][nt][1] + bv1;
            stg[(r + 8) * 132 + c]     = acc[mt][nt][2] + bv0;
            stg[(r + 8) * 132 + c + 1] = acc[mt][nt][3] + bv1;
        }
    }
    __syncthreads();
    for (int row = wid; row < 128; row += 8) {
        int m = m0 + row;
        float* op = Cp + (size_t)m * NT + n0;
        for (int c = lid; c < 128; c += 32) op[c] = stg[row * 132 + c];
    }
}

// ================= fp8 logits GEMM (m16n8k32 e4m3), K=512 =================
// MODE 0: lse partials only (no logits written).
// MODE 1: recompute; write fp32 out with lse subtracted.
#define SP8 80

template <int MODE>
__global__ void __launch_bounds__(256) bmma_logits8(const unsigned char* __restrict__ A8,
                                                    const unsigned char* __restrict__ B8,
                                                    const float* __restrict__ bias,
                                                    float* __restrict__ outp) {
    extern __shared__ char smem[];
    unsigned char* Asp = reinterpret_cast<unsigned char*>(smem);
    unsigned char* Bsp = reinterpret_cast<unsigned char*>(smem) + 10240;
    const int tid = threadIdx.x, wid = tid >> 5, lid = tid & 31;
    const int gid = lid >> 2, tig = lid & 3;
    const int n0 = blockIdx.x * 128;
    const int m0 = blockIdx.y * 128;
    const int wm = (wid >> 2) * 64;
    const int wn = (wid & 3) * 32;

    float acc[4][4][4];
#pragma unroll
    for (int i = 0; i < 4; i++)
#pragma unroll
        for (int j = 0; j < 4; j++)
#pragma unroll
            for (int r = 0; r < 4; r++) acc[i][j][r] = 0.f;

    const int li0 = tid * 2, li1 = tid * 2 + 1;
    const int ar0 = li0 >> 2, ag0 = li0 & 3, ar1 = li1 >> 2, ag1 = li1 & 3;
    int bn0 = n0 + ar0; if (bn0 > VOCAB1 - 1) bn0 = VOCAB1 - 1;
    int bn1 = n0 + ar1; if (bn1 > VOCAB1 - 1) bn1 = VOCAB1 - 1;

    uint4 pa0, pa1, pb0, pb1;
    pa0 = *reinterpret_cast<const uint4*>(A8 + (size_t)(m0 + ar0) * DIN + ag0 * 16);
    pa1 = *reinterpret_cast<const uint4*>(A8 + (size_t)(m0 + ar1) * DIN + ag1 * 16);
    pb0 = *reinterpret_cast<const uint4*>(B8 + (size_t)bn0 * DIN + ag0 * 16);
    pb1 = *reinterpret_cast<const uint4*>(B8 + (size_t)bn1 * DIN + ag1 * 16);

    for (int kc = 0; kc < 8; kc++) {
        __syncthreads();
        *reinterpret_cast<uint4*>(Asp + ar0 * SP8 + ag0 * 16) = pa0;
        *reinterpret_cast<uint4*>(Asp + ar1 * SP8 + ag1 * 16) = pa1;
        *reinterpret_cast<uint4*>(Bsp + ar0 * SP8 + ag0 * 16) = pb0;
        *reinterpret_cast<uint4*>(Bsp + ar1 * SP8 + ag1 * 16) = pb1;
        __syncthreads();
        if (kc < 7) {
            int k0 = (kc + 1) * 64;
            pa0 = *reinterpret_cast<const uint4*>(A8 + (size_t)(m0 + ar0) * DIN + k0 + ag0 * 16);
            pa1 = *reinterpret_cast<const uint4*>(A8 + (size_t)(m0 + ar1) * DIN + k0 + ag1 * 16);
            pb0 = *reinterpret_cast<const uint4*>(B8 + (size_t)bn0 * DIN + k0 + ag0 * 16);
            pb1 = *reinterpret_cast<const uint4*>(B8 + (size_t)bn1 * DIN + k0 + ag1 * 16);
        }
#pragma unroll
        for (int ks = 0; ks < 64; ks += 32) {
            uint32_t af[4][4], bf[4][2];
#pragma unroll
            for (int mt = 0; mt < 4; mt++) {
                int r = wm + mt * 16 + gid;
                const unsigned char* ap = Asp + r * SP8 + ks + tig * 4;
                af[mt][0] = *reinterpret_cast<const uint32_t*>(ap);
                af[mt][1] = *reinterpret_cast<const uint32_t*>(ap + 8 * SP8);
                af[mt][2] = *reinterpret_cast<const uint32_t*>(ap + 16);
                af[mt][3] = *reinterpret_cast<const uint32_t*>(ap + 8 * SP8 + 16);
            }
#pragma unroll
            for (int nt = 0; nt < 4; nt++) {
                int n = wn + nt * 8 + gid;
                const unsigned char* bp = Bsp + n * SP8 + ks + tig * 4;
                bf[nt][0] = *reinterpret_cast<const uint32_t*>(bp);
                bf[nt][1] = *reinterpret_cast<const uint32_t*>(bp + 16);
            }
#pragma unroll
            for (int mt = 0; mt < 4; mt++)
#pragma unroll
                for (int nt = 0; nt < 4; nt++)
                    mma_fp8(acc[mt][nt], af[mt][0], af[mt][1], af[mt][2], af[mt][3],
                            bf[nt][0], bf[nt][1]);
        }
    }

    __syncthreads();
    float* stg = reinterpret_cast<float*>(smem);
    const float SC = 1.f / 4096.f;
#pragma unroll
    for (int mt = 0; mt < 4; mt++) {
#pragma unroll
        for (int nt = 0; nt < 4; nt++) {
            int r = wm + mt * 16 + gid;
            int c = wn + nt * 8 + tig * 2;
            int n = n0 + c;
            int ncl = (n > VOCAB1 - 1) ? VOCAB1 - 1 : n;
            int ncl1 = (n + 1 > VOCAB1 - 1) ? VOCAB1 - 1 : n + 1;
            float bv0 = bias[ncl], bv1 = bias[ncl1];
            stg[r * 132 + c]           = acc[mt][nt][0] * SC + bv0;
            stg[r * 132 + c + 1]       = acc[mt][nt][1] * SC + bv1;
            stg[(r + 8) * 132 + c]     = acc[mt][nt][2] * SC + bv0;
            stg[(r + 8) * 132 + c + 1] = acc[mt][nt][3] * SC + bv1;
        }
    }
    __syncthreads();
    int nmax = VOCAB1 - n0;
    if (nmax > 128) nmax = 128;
    for (int row = wid; row < 128; row += 8) {
        int m = m0 + row;
        int t = m >> 6, b = m & 63;
        int r_out = b * TT + t;
        float v0 = -INFINITY, v1 = -INFINITY, v2 = -INFINITY, v3 = -INFINITY;
        int c0 = lid, c1 = lid + 32, c2 = lid + 64, c3 = lid + 96;
        if (c0 < nmax) v0 = stg[row * 132 + c0];
        if (c1 < nmax) v1 = stg[row * 132 + c1];
        if (c2 < nmax) v2 = stg[row * 132 + c2];
        if (c3 < nmax) v3 = stg[row * 132 + c3];
        if (MODE == 0) {
            float mx = fmaxf(fmaxf(v0, v1), fmaxf(v2, v3));
#pragma unroll
            for (int o = 16; o > 0; o >>= 1)
                mx = fmaxf(mx, __shfl_xor_sync(0xffffffffu, mx, o));
            float s = 0.f;
            if (c0 < nmax) s += __expf(v0 - mx);
            if (c1 < nmax) s += __expf(v1 - mx);
            if (c2 < nmax) s += __expf(v2 - mx);
            if (c3 < nmax) s += __expf(v3 - mx);
#pragma unroll
            for (int o = 16; o > 0; o >>= 1)
                s += __shfl_xor_sync(0xffffffffu, s, o);
            if (lid == 0) {
                g_pmax[(size_t)r_out * NBLK_LG + blockIdx.x] = mx;
                g_psum[(size_t)r_out * NBLK_LG + blockIdx.x] = s;
            }
        } else {
            float l = g_lse[r_out];
            float* op = outp + (size_t)r_out * VOCAB1 + n0;
            if (c0 < nmax) op[c0] = v0 - l;
            if (c1 < nmax) op[c1] = v1 - l;
            if (c2 < nmax) op[c2] = v2 - l;
            if (c3 < nmax) op[c3] = v3 - l;
        }
    }
}

// ================= lse reduce =================
__global__ void lse_reduce() {
    int row = blockIdx.x * 8 + (threadIdx.x >> 5);
    int lid = threadIdx.x & 31;
    float m = -INFINITY, s = 0.f;
    for (int i = lid; i < NBLK_LG; i += 32) {
        float m2 = g_pmax[(size_t)row * NBLK_LG + i];
        float s2 = g_psum[(size_t)row * NBLK_LG + i];
        if (m2 > m) { s = s * __expf(m - m2) + s2; m = m2; }
        else        { s += s2 * __expf(m2 - m); }
    }
#pragma unroll
    for (int o = 16; o > 0; o >>= 1) {
        float m2 = __shfl_xor_sync(0xffffffffu, m, o);
        float s2 = __shfl_xor_sync(0xffffffffu, s, o);
        if (m2 > m) { s = s * __expf(m - m2) + s2; m = m2; }
        else        { s += s2 * __expf(m2 - m); }
    }
    if (lid == 0) g_lse[row] = m + logf(s);
}

// ================= launch =================
extern "C" void kernel_launch(void* const* d_in, const int* in_sizes, int n_in,
                              void* d_out, int out_size) {
    const float* img_feat = (const float*)d_in[0];
    const int*   seq      = (const int*)d_in[1];
    const float* W_img    = (const float*)d_in[2];
    const float* b_img    = (const float*)d_in[3];
    const float* embed    = (const float*)d_in[4];
    const float* W_ih     = (const float*)d_in[5];
    const float* b_ih     = (const float*)d_in[6];
    const float* W_hh     = (const float*)d_in[7];
    const float* b_hh     = (const float*)d_in[8];
    const float* W_logit  = (const float*)d_in[9];
    const float* b_logit  = (const float*)d_in[10];
    float* out = (float*)d_out;

    float *gx, *bias2;
    __nv_bfloat16 *xsb, *wib;
    unsigned char *hs8, *wl8;
    cudaGetSymbolAddress((void**)&gx,    g_gx);
    cudaGetSymbolAddress((void**)&bias2, g_bias2);
    cudaGetSymbolAddress((void**)&xsb,   g_xsb);
    cudaGetSymbolAddress((void**)&hs8,   g_hs8);
    cudaGetSymbolAddress((void**)&wl8,   g_wl8);
    cudaGetSymbolAddress((void**)&wib,   g_wib);

    cudaFuncSetAttribute(bmma_gates,      cudaFuncAttributeMaxDynamicSharedMemorySize, LG_DSMEM);
    cudaFuncSetAttribute(bmma_logits8<0>, cudaFuncAttributeMaxDynamicSharedMemorySize, LG_DSMEM);
    cudaFuncSetAttribute(bmma_logits8<1>, cudaFuncAttributeMaxDynamicSharedMemorySize, LG_DSMEM);
    cudaFuncSetAttribute(lstm_persist64,  cudaFuncAttributeMaxDynamicSharedMemorySize, ST_SMEM);

    init_gather<<<1216, 128>>>(seq, embed, b_ih, b_hh);
    conv_all<<<CONV_BLOCKS, 256>>>(W_logit, W_ih, W_hh);
    x0_ksplit<<<dim3(8, 8), 256>>>(img_feat, W_img);
    x0_reduce<<<(BB * DIN) / 256, 256>>>(b_img);
    bmma_gates<<<dim3(16, 10), 256, LG_DSMEM>>>(xsb, wib, bias2, gx);
    lstm_persist64<<<64, 256, ST_SMEM>>>();
    // pass 1: lse partials only
    bmma_logits8<0><<<dim3(NBLK_LG, 10), 256, LG_DSMEM>>>(hs8, wl8, b_logit, nullptr);
    lse_reduce<<<BB * TT / 8, 256>>>();
    // pass 2: recompute, write fp32 out with lse subtracted
    bmma_logits8<1><<<dim3(NBLK_LG, 10), 256, LG_DSMEM>>>(hs8, wl8, b_logit, out);
}

// round 14
// speedup vs baseline: 1.3641x; 1.3641x over previous
#include <cuda_runtime.h>
#include <cuda_bf16.h>
#include <cuda_fp8.h>
#include <math.h>
#include <stdint.h>

#define VOCAB1 32001
#define VP     32004
#define DIN 512
#define DR  512
#define DF  2048
#define BB  64
#define TT  20
#define G4  2048
#define NBLK_LG 251

// ================= device scratch =================
__device__ __align__(16) __nv_bfloat16 g_xsb[TT * BB * DIN];
__device__ __align__(16) float g_gx[(size_t)TT * BB * G4];
__device__ __align__(16) float g_c[BB * DR];
__device__ __align__(16) __nv_bfloat16 g_hb[BB * DR];
__device__ __align__(16) unsigned char g_hs8[TT * BB * DR];
__device__ __align__(16) unsigned char g_wl8[(size_t)VOCAB1 * DR];
__device__ __align__(16) __nv_bfloat16 g_wib[(size_t)G4 * DIN];
__device__ __align__(16) __nv_bfloat16 g_whb[(size_t)G4 * DR];
__device__ __align__(16) float g_bias2[G4];
__device__ __align__(16) float g_lse[BB * TT];
__device__ __align__(16) float g_x0p[8 * BB * DIN];
__device__ __align__(16) float g_pmax[BB * TT * NBLK_LG];
__device__ __align__(16) float g_psum[BB * TT * NBLK_LG];
__device__ __align__(16) __nv_bfloat16 g_lgb[(size_t)BB * TT * VP];
__device__ int g_cnt;

// ================= fused init + embedding gather =================
__global__ void init_gather(const int* __restrict__ seq, const float* __restrict__ embed,
                            const float* __restrict__ b_ih, const float* __restrict__ b_hh) {
    int bid = blockIdx.x, tid = threadIdx.x;
    int id = bid * 128 + tid;
    if (id < BB * DR) g_c[id] = 0.f;
    if (id < G4) g_bias2[id] = b_ih[id] + b_hh[id];
    if (id == 0) g_cnt = 0;

    int t = 1 + (bid >> 6), b = bid & 63;
    int idx = seq[b * TT + t];
    if (idx < 0) idx = 0;
    if (idx > VOCAB1 - 1) idx = VOCAB1 - 1;
    float4 v = reinterpret_cast<const float4*>(embed + (size_t)idx * DIN)[tid];
    __nv_bfloat162 p0 = __floats2bfloat162_rn(v.x, v.y);
    __nv_bfloat162 p1 = __floats2bfloat162_rn(v.z, v.w);
    uint2 u;
    u.x = *reinterpret_cast<uint32_t*>(&p0);
    u.y = *reinterpret_cast<uint32_t*>(&p1);
    reinterpret_cast<uint2*>(g_xsb + ((size_t)t * BB + b) * DIN)[tid] = u;
}

// ================= fused weight conversion =================
#define NQ_WL ((size_t)VOCAB1 * DR / 4)
#define NQ_WI ((size_t)G4 * DIN / 4)
#define NQ_WH ((size_t)G4 * DR / 4)
__global__ void conv_all(const float* __restrict__ wl, const float* __restrict__ wi,
                         const float* __restrict__ wh) {
    size_t q = (size_t)blockIdx.x * blockDim.x + threadIdx.x;
    if (q < NQ_WL) {
        size_t i = q * 4;
        float4 v = *reinterpret_cast<const float4*>(wl + i);
        uint32_t r =
            (uint32_t)__nv_cvt_float_to_fp8(v.x * 64.f, __NV_SATFINITE, __NV_E4M3)
          | ((uint32_t)__nv_cvt_float_to_fp8(v.y * 64.f, __NV_SATFINITE, __NV_E4M3) << 8)
          | ((uint32_t)__nv_cvt_float_to_fp8(v.z * 64.f, __NV_SATFINITE, __NV_E4M3) << 16)
          | ((uint32_t)__nv_cvt_float_to_fp8(v.w * 64.f, __NV_SATFINITE, __NV_E4M3) << 24);
        *reinterpret_cast<uint32_t*>(g_wl8 + i) = r;
        return;
    }
    q -= NQ_WL;
    const float* src;
    __nv_bfloat16* dst;
    if (q < NQ_WI) { src = wi; dst = g_wib; }
    else if (q < NQ_WI + NQ_WH) { q -= NQ_WI; src = wh; dst = g_whb; }
    else return;
    size_t i = q * 4;
    float4 v = *reinterpret_cast<const float4*>(src + i);
    __nv_bfloat162 p0 = __floats2bfloat162_rn(v.x, v.y);
    __nv_bfloat162 p1 = __floats2bfloat162_rn(v.z, v.w);
    uint2 u;
    u.x = *reinterpret_cast<uint32_t*>(&p0);
    u.y = *reinterpret_cast<uint32_t*>(&p1);
    *reinterpret_cast<uint2*>(&dst[i]) = u;
}
#define CONV_BLOCKS ((int)((NQ_WL + NQ_WI + NQ_WH + 255) / 256))

// ================= x0: k-split fp32 GEMM =================
__global__ void x0_ksplit(const float* __restrict__ A, const float* __restrict__ Bm) {
    __shared__ float As[16][64];
    __shared__ float Bs[16][64];
    const int tid = threadIdx.x;
    const int n0 = blockIdx.x * 64;
    const int kbeg = blockIdx.y * 256;
    const int tx = tid & 15, ty = tid >> 4;
    float acc[4][4] = {};
    for (int kt = 0; kt < 256; kt += 16) {
        {
            int row = tid >> 2, kq = (tid & 3) << 2;
            float4 v = *reinterpret_cast<const float4*>(A + (size_t)row * DF + kbeg + kt + kq);
            As[kq + 0][row] = v.x; As[kq + 1][row] = v.y;
            As[kq + 2][row] = v.z; As[kq + 3][row] = v.w;
        }
        {
            int row = tid >> 2, kq = (tid & 3) << 2;
            float4 v = *reinterpret_cast<const float4*>(Bm + (size_t)(n0 + row) * DF + kbeg + kt + kq);
            Bs[kq + 0][row] = v.x; Bs[kq + 1][row] = v.y;
            Bs[kq + 2][row] = v.z; Bs[kq + 3][row] = v.w;
        }
        __syncthreads();
#pragma unroll
        for (int k = 0; k < 16; k++) {
            float a[4], b[4];
#pragma unroll
            for (int i = 0; i < 4; i++) a[i] = As[k][ty * 4 + i];
#pragma unroll
            for (int j = 0; j < 4; j++) b[j] = Bs[k][tx * 4 + j];
#pragma unroll
            for (int i = 0; i < 4; i++)
#pragma unroll
                for (int j = 0; j < 4; j++) acc[i][j] = fmaf(a[i], b[j], acc[i][j]);
        }
        __syncthreads();
    }
    float* p = g_x0p + (size_t)blockIdx.y * BB * DIN;
#pragma unroll
    for (int i = 0; i < 4; i++)
#pragma unroll
        for (int j = 0; j < 4; j++)
            p[(ty * 4 + i) * DIN + n0 + tx * 4 + j] = acc[i][j];
}

__global__ void x0_reduce(const float* __restrict__ b_img) {
    int id = blockIdx.x * blockDim.x + threadIdx.x;
    float s = b_img[id & 511];
#pragma unroll
    for (int kb = 0; kb < 8; kb++) s += g_x0p[kb * BB * DIN + id];
    g_xsb[id] = __float2bfloat16(s);
}

// ================= mma primitives =================
__device__ __forceinline__ void mma16816(float* d, uint32_t a0, uint32_t a1,
                                         uint32_t a2, uint32_t a3,
                                         uint32_t b0, uint32_t b1) {
    asm volatile(
        "mma.sync.aligned.m16n8k16.row.col.f32.bf16.bf16.f32 "
        "{%0,%1,%2,%3}, {%4,%5,%6,%7}, {%8,%9}, {%0,%1,%2,%3};"
        : "+f"(d[0]), "+f"(d[1]), "+f"(d[2]), "+f"(d[3])
        : "r"(a0), "r"(a1), "r"(a2), "r"(a3), "r"(b0), "r"(b1));
}

__device__ __forceinline__ void mma_fp8(float* d, uint32_t a0, uint32_t a1,
                                        uint32_t a2, uint32_t a3,
                                        uint32_t b0, uint32_t b1) {
    asm volatile(
        "mma.sync.aligned.m16n8k32.row.col.f32.e4m3.e4m3.f32 "
        "{%0,%1,%2,%3}, {%4,%5,%6,%7}, {%8,%9}, {%0,%1,%2,%3};"
        : "+f"(d[0]), "+f"(d[1]), "+f"(d[2]), "+f"(d[3])
        : "r"(a0), "r"(a1), "r"(a2), "r"(a3), "r"(b0), "r"(b1));
}

__device__ __forceinline__ float sigmoidf_(float x) { return 1.f / (1.f + __expf(-x)); }

__device__ __forceinline__ uint4 ldcg_v4(const uint4* p) {
    uint4 v;
    asm volatile("ld.global.cg.v4.u32 {%0,%1,%2,%3}, [%4];"
                 : "=r"(v.x), "=r"(v.y), "=r"(v.z), "=r"(v.w) : "l"(p));
    return v;
}

__device__ __forceinline__ void cp16(uint32_t smem_dst, const void* gsrc) {
    asm volatile("cp.async.cg.shared.global [%0], [%1], 16;" :: "r"(smem_dst), "l"(gsrc));
}
#define CP_COMMIT() asm volatile("cp.async.commit_group;" ::: "memory")
#define CP_WAIT(n)  asm volatile("cp.async.wait_group %0;" :: "n"(n) : "memory")

// ================= persistent LSTM (64 CTAs, single launch) =================
#define HSTR 520
#define ST_SMEM (64 * HSTR * 2 + 32 * HSTR * 2 + 64 * 33 * 4)

__global__ void __launch_bounds__(256) lstm_persist64() {
    extern __shared__ char smem[];
    __nv_bfloat16* hS = reinterpret_cast<__nv_bfloat16*>(smem);
    __nv_bfloat16* wS = reinterpret_cast<__nv_bfloat16*>(smem + 64 * HSTR * 2);
    float* gS = reinterpret_cast<float*>(smem + 64 * HSTR * 2 + 32 * HSTR * 2);
    const int tid = threadIdx.x, wid = tid >> 5, lid = tid & 31;
    const int gid = lid >> 2, tig = lid & 3;
    const int cta = blockIdx.x;
    const int c0 = cta * 8;

    for (int q = tid; q < 2048; q += 256) {
        int j = q >> 6, g = q & 63;
        int wr = (j >> 3) * 512 + c0 + (j & 7);
        *reinterpret_cast<uint4*>(wS + j * HSTR + g * 8) =
            reinterpret_cast<const uint4*>(g_whb + (size_t)wr * DR)[g];
    }
    __syncthreads();

    const int mrow = (wid >> 1) * 16;
    const int ncol = (wid & 1) * 16;

    for (int t = 0; t < TT; t++) {
        if (t > 0) {
            if (tid == 0) {
                int target = 64 * t, v;
                long guard = 0;
                do {
                    asm volatile("ld.global.cg.s32 %0, [%1];" : "=r"(v) : "l"(&g_cnt));
                } while (v < target && ++guard < (1L << 31));
            }
            __syncthreads();
            {
                const uint4* src = reinterpret_cast<const uint4*>(g_hb);
                for (int q = tid; q < 4096; q += 256) {
                    int row = q >> 6, g = q & 63;
                    *reinterpret_cast<uint4*>(hS + row * HSTR + g * 8) = ldcg_v4(src + row * 64 + g);
                }
            }
            __syncthreads();
            float acc[2][4] = {};
#pragma unroll 4
            for (int ks = 0; ks < 512; ks += 16) {
                const __nv_bfloat16* ap = hS + (mrow + gid) * HSTR + ks + tig * 2;
                uint32_t a0 = *reinterpret_cast<const uint32_t*>(ap);
                uint32_t a1 = *reinterpret_cast<const uint32_t*>(ap + 8 * HSTR);
                uint32_t a2 = *reinterpret_cast<const uint32_t*>(ap + 8);
                uint32_t a3 = *reinterpret_cast<const uint32_t*>(ap + 8 * HSTR + 8);
#pragma unroll
                for (int nt = 0; nt < 2; nt++) {
                    const __nv_bfloat16* bp = wS + (ncol + nt * 8 + gid) * HSTR + ks + tig * 2;
                    uint32_t b0 = *reinterpret_cast<const uint32_t*>(bp);
                    uint32_t b1 = *reinterpret_cast<const uint32_t*>(bp + 8);
                    mma16816(acc[nt], a0, a1, a2, a3, b0, b1);
                }
            }
#pragma unroll
            for (int nt = 0; nt < 2; nt++) {
                int r0 = mrow + gid;
                int c = ncol + nt * 8 + tig * 2;
                gS[r0 * 33 + c]           = acc[nt][0];
                gS[r0 * 33 + c + 1]       = acc[nt][1];
                gS[(r0 + 8) * 33 + c]     = acc[nt][2];
                gS[(r0 + 8) * 33 + c + 1] = acc[nt][3];
            }
            __syncthreads();
        }

#pragma unroll
        for (int e = tid; e < 512; e += 256) {
            int b = e >> 3, jl = e & 7;
            int r = c0 + jl;
            const float* gxp = g_gx + ((size_t)t * BB + b) * G4;
            float gi = gxp[r], gf = gxp[512 + r], gg = gxp[1024 + r], go = gxp[1536 + r];
            if (t > 0) {
                gi += gS[b * 33 + jl];
                gf += gS[b * 33 + 8 + jl];
                gg += gS[b * 33 + 16 + jl];
                go += gS[b * 33 + 24 + jl];
            }
            int id = b * DR + r;
            float c = (t > 0) ? g_c[id] : 0.f;
            float cn = sigmoidf_(gf) * c + sigmoidf_(gi) * tanhf(gg);
            float hn = sigmoidf_(go) * tanhf(cn);
            g_c[id] = cn;
            g_hb[id] = __float2bfloat16(hn);
            g_hs8[(size_t)t * BB * DR + id] =
                __nv_cvt_float_to_fp8(hn * 64.f, __NV_SATFINITE, __NV_E4M3);
        }
        __syncthreads();
        if (tid == 0) {
            __threadfence();
            atomicAdd(&g_cnt, 1);
        }
    }
}

// ================= bf16 mma GEMM (gates_x), K=512 =================
#define SP 40
#define LG_DSMEM (128 * 132 * 4)

__global__ void __launch_bounds__(256) bmma_gates(const __nv_bfloat16* __restrict__ Abm,
                                                  const __nv_bfloat16* __restrict__ Bbm,
                                                  const float* __restrict__ bias,
                                                  float* __restrict__ Cp) {
    extern __shared__ char smem[];
    __nv_bfloat16* Asp = reinterpret_cast<__nv_bfloat16*>(smem);
    __nv_bfloat16* Bsp = reinterpret_cast<__nv_bfloat16*>(smem + 10240);
    const int tid = threadIdx.x, wid = tid >> 5, lid = tid & 31;
    const int gid = lid >> 2, tig = lid & 3;
    const int n0 = blockIdx.x * 128;
    const int m0 = blockIdx.y * 128;
    const int wm = (wid >> 2) * 64;
    const int wn = (wid & 3) * 32;
    const int NT = G4;

    float acc[4][4][4];
#pragma unroll
    for (int i = 0; i < 4; i++)
#pragma unroll
        for (int j = 0; j < 4; j++)
#pragma unroll
            for (int r = 0; r < 4; r++) acc[i][j][r] = 0.f;

    const int li0 = tid * 2, li1 = tid * 2 + 1;
    const int ar0 = li0 >> 2, ag0 = li0 & 3, ar1 = li1 >> 2, ag1 = li1 & 3;

    uint4 pa0, pa1, pb0, pb1;
    pa0 = *reinterpret_cast<const uint4*>(Abm + (size_t)(m0 + ar0) * DIN + ag0 * 8);
    pa1 = *reinterpret_cast<const uint4*>(Abm + (size_t)(m0 + ar1) * DIN + ag1 * 8);
    pb0 = *reinterpret_cast<const uint4*>(Bbm + (size_t)(n0 + ar0) * DIN + ag0 * 8);
    pb1 = *reinterpret_cast<const uint4*>(Bbm + (size_t)(n0 + ar1) * DIN + ag1 * 8);

    for (int kt = 0; kt < 16; kt++) {
        __syncthreads();
        *reinterpret_cast<uint4*>(Asp + ar0 * SP + ag0 * 8) = pa0;
        *reinterpret_cast<uint4*>(Asp + ar1 * SP + ag1 * 8) = pa1;
        *reinterpret_cast<uint4*>(Bsp + ar0 * SP + ag0 * 8) = pb0;
        *reinterpret_cast<uint4*>(Bsp + ar1 * SP + ag1 * 8) = pb1;
        __syncthreads();
        if (kt < 15) {
            int k0 = (kt + 1) * 32;
            pa0 = *reinterpret_cast<const uint4*>(Abm + (size_t)(m0 + ar0) * DIN + k0 + ag0 * 8);
            pa1 = *reinterpret_cast<const uint4*>(Abm + (size_t)(m0 + ar1) * DIN + k0 + ag1 * 8);
            pb0 = *reinterpret_cast<const uint4*>(Bbm + (size_t)(n0 + ar0) * DIN + k0 + ag0 * 8);
            pb1 = *reinterpret_cast<const uint4*>(Bbm + (size_t)(n0 + ar1) * DIN + k0 + ag1 * 8);
        }
#pragma unroll
        for (int ks = 0; ks < 32; ks += 16) {
            uint32_t af[4][4], bf[4][2];
#pragma unroll
            for (int mt = 0; mt < 4; mt++) {
                int r = wm + mt * 16 + gid;
                int k = ks + tig * 2;
                af[mt][0] = *reinterpret_cast<const uint32_t*>(Asp + r * SP + k);
                af[mt][1] = *reinterpret_cast<const uint32_t*>(Asp + (r + 8) * SP + k);
                af[mt][2] = *reinterpret_cast<const uint32_t*>(Asp + r * SP + k + 8);
                af[mt][3] = *reinterpret_cast<const uint32_t*>(Asp + (r + 8) * SP + k + 8);
            }
#pragma unroll
            for (int nt = 0; nt < 4; nt++) {
                int n = wn + nt * 8 + gid;
                int k = ks + tig * 2;
                bf[nt][0] = *reinterpret_cast<const uint32_t*>(Bsp + n * SP + k);
                bf[nt][1] = *reinterpret_cast<const uint32_t*>(Bsp + n * SP + k + 8);
            }
#pragma unroll
            for (int mt = 0; mt < 4; mt++)
#pragma unroll
                for (int nt = 0; nt < 4; nt++)
                    mma16816(acc[mt][nt], af[mt][0], af[mt][1], af[mt][2], af[mt][3],
                             bf[nt][0], bf[nt][1]);
        }
    }

    __syncthreads();
    float* stg = reinterpret_cast<float*>(smem);
#pragma unroll
    for (int mt = 0; mt < 4; mt++) {
#pragma unroll
        for (int nt = 0; nt < 4; nt++) {
            int r = wm + mt * 16 + gid;
            int c = wn + nt * 8 + tig * 2;
            int n = n0 + c;
            float bv0 = bias[n], bv1 = bias[n + 1];
            stg[r * 132 + c]           = acc[mt][nt][0] + bv0;
            stg[r * 132 + c + 1]       = acc[mt][nt][1] + bv1;
            stg[(r + 8) * 132 + c]     = acc[mt][nt][2] + bv0;
            stg[(r + 8) * 132 + c + 1] = acc[mt][nt][3] + bv1;
        }
    }
    __syncthreads();
    for (int row = wid; row < 128; row += 8) {
        int m = m0 + row;
        float* op = Cp + (size_t)m * NT + n0;
        for (int c = lid; c < 128; c += 32) op[c] = stg[row * 132 + c];
    }
}

// ================= fp8 logits GEMM: cp.async 2-stage pipeline, half-tile epilogue =================
#define SP8 80
#define LG8_STAGE 20480               // A(10240)+B(10240) per stage
#define LG8_DSMEM (2 * LG8_STAGE)     // 40960; epilogue staging (33792) reuses stage0

__global__ void __launch_bounds__(256) bmma_logits8(const unsigned char* __restrict__ A8,
                                                    const unsigned char* __restrict__ B8,
                                                    const float* __restrict__ bias,
                                                    __nv_bfloat16* __restrict__ Cp) {
    extern __shared__ char smem[];
    uint32_t sb;
    asm("{ .reg .u64 t; cvta.to.shared.u64 t, %1; cvt.u32.u64 %0, t; }" : "=r"(sb) : "l"(smem));
    const int tid = threadIdx.x, wid = tid >> 5, lid = tid & 31;
    const int gid = lid >> 2, tig = lid & 3;
    const int n0 = blockIdx.x * 128;
    const int m0 = blockIdx.y * 128;
    const int wm = (wid >> 2) * 64;
    const int wn = (wid & 3) * 32;

    float acc[4][4][4];
#pragma unroll
    for (int i = 0; i < 4; i++)
#pragma unroll
        for (int j = 0; j < 4; j++)
#pragma unroll
            for (int r = 0; r < 4; r++) acc[i][j][r] = 0.f;

    // loader mapping: li in [0,512): row = li>>2, seg16 = li&3
    const int li0 = tid * 2, li1 = tid * 2 + 1;
    const int ar0 = li0 >> 2, ag0 = li0 & 3, ar1 = li1 >> 2, ag1 = li1 & 3;
    int bn0 = n0 + ar0; if (bn0 > VOCAB1 - 1) bn0 = VOCAB1 - 1;
    int bn1 = n0 + ar1; if (bn1 > VOCAB1 - 1) bn1 = VOCAB1 - 1;
    const unsigned char* aS0 = A8 + (size_t)(m0 + ar0) * DIN + ag0 * 16;
    const unsigned char* aS1 = A8 + (size_t)(m0 + ar1) * DIN + ag1 * 16;
    const unsigned char* bS0 = B8 + (size_t)bn0 * DIN + ag0 * 16;
    const unsigned char* bS1 = B8 + (size_t)bn1 * DIN + ag1 * 16;
    const uint32_t dA0 = ar0 * SP8 + ag0 * 16, dA1 = ar1 * SP8 + ag1 * 16;
    const uint32_t dB0 = 10240 + ar0 * SP8 + ag0 * 16, dB1 = 10240 + ar1 * SP8 + ag1 * 16;

    // prologue: chunk 0 -> stage 0
    cp16(sb + dA0, aS0); cp16(sb + dA1, aS1);
    cp16(sb + dB0, bS0); cp16(sb + dB1, bS1);
    CP_COMMIT();

    for (int kc = 0; kc < 8; kc++) {
        const uint32_t st = (uint32_t)(kc & 1) * LG8_STAGE;
        if (kc < 7) {
            const uint32_t st2 = (uint32_t)((kc + 1) & 1) * LG8_STAGE;
            int k0 = (kc + 1) * 64;
            cp16(sb + st2 + dA0, aS0 + k0); cp16(sb + st2 + dA1, aS1 + k0);
            cp16(sb + st2 + dB0, bS0 + k0); cp16(sb + st2 + dB1, bS1 + k0);
            CP_COMMIT();
            CP_WAIT(1);
        } else {
            CP_WAIT(0);
        }
        __syncthreads();
        const unsigned char* Asp = reinterpret_cast<const unsigned char*>(smem) + st;
        const unsigned char* Bsp = Asp + 10240;
#pragma unroll
        for (int ks = 0; ks < 64; ks += 32) {
            uint32_t af[4][4], bf[4][2];
#pragma unroll
            for (int mt = 0; mt < 4; mt++) {
                int r = wm + mt * 16 + gid;
                const unsigned char* ap = Asp + r * SP8 + ks + tig * 4;
                af[mt][0] = *reinterpret_cast<const uint32_t*>(ap);
                af[mt][1] = *reinterpret_cast<const uint32_t*>(ap + 8 * SP8);
                af[mt][2] = *reinterpret_cast<const uint32_t*>(ap + 16);
                af[mt][3] = *reinterpret_cast<const uint32_t*>(ap + 8 * SP8 + 16);
            }
#pragma unroll
            for (int nt = 0; nt < 4; nt++) {
                int n = wn + nt * 8 + gid;
                const unsigned char* bp = Bsp + n * SP8 + ks + tig * 4;
                bf[nt][0] = *reinterpret_cast<const uint32_t*>(bp);
                bf[nt][1] = *reinterpret_cast<const uint32_t*>(bp + 16);
            }
#pragma unroll
            for (int mt = 0; mt < 4; mt++)
#pragma unroll
                for (int nt = 0; nt < 4; nt++)
                    mma_fp8(acc[mt][nt], af[mt][0], af[mt][1], af[mt][2], af[mt][3],
                            bf[nt][0], bf[nt][1]);
        }
        __syncthreads();   // stage consumed before next overwrite
    }

    // ===== epilogue: two half-tiles of 64 rows (stg = 64*132 floats, reuses smem) =====
    float* stg = reinterpret_cast<float*>(smem);
    const float SC = 1.f / 4096.f;
    int nmax = VOCAB1 - n0;
    if (nmax > 128) nmax = 128;
#pragma unroll
    for (int h = 0; h < 2; h++) {
        // warps whose wm matches this half stage their fragments
        if (wm == h * 64) {
#pragma unroll
            for (int mt = 0; mt < 4; mt++) {
#pragma unroll
                for (int nt = 0; nt < 4; nt++) {
                    int r = mt * 16 + gid;            // row within half
                    int c = wn + nt * 8 + tig * 2;
                    int n = n0 + c;
                    int ncl = (n > VOCAB1 - 1) ? VOCAB1 - 1 : n;
                    int ncl1 = (n + 1 > VOCAB1 - 1) ? VOCAB1 - 1 : n + 1;
                    float bv0 = bias[ncl], bv1 = bias[ncl1];
                    stg[r * 132 + c]           = acc[mt][nt][0] * SC + bv0;
                    stg[r * 132 + c + 1]       = acc[mt][nt][1] * SC + bv1;
                    stg[(r + 8) * 132 + c]     = acc[mt][nt][2] * SC + bv0;
                    stg[(r + 8) * 132 + c + 1] = acc[mt][nt][3] * SC + bv1;
                }
            }
        }
        __syncthreads();
        for (int r2 = wid; r2 < 64; r2 += 8) {
            int m = m0 + h * 64 + r2;
            int t = m >> 6, b = m & 63;
            int r_out = b * TT + t;
            __nv_bfloat16* op = Cp + (size_t)r_out * VP + n0;
            float v0 = -INFINITY, v1 = -INFINITY, v2 = -INFINITY, v3 = -INFINITY;
            int c0 = lid, c1 = lid + 32, c2 = lid + 64, c3 = lid + 96;
            if (c0 < nmax) { v0 = stg[r2 * 132 + c0]; op[c0] = __float2bfloat16(v0); }
            if (c1 < nmax) { v1 = stg[r2 * 132 + c1]; op[c1] = __float2bfloat16(v1); }
            if (c2 < nmax) { v2 = stg[r2 * 132 + c2]; op[c2] = __float2bfloat16(v2); }
            if (c3 < nmax) { v3 = stg[r2 * 132 + c3]; op[c3] = __float2bfloat16(v3); }
            float mx = fmaxf(fmaxf(v0, v1), fmaxf(v2, v3));
#pragma unroll
            for (int o = 16; o > 0; o >>= 1)
                mx = fmaxf(mx, __shfl_xor_sync(0xffffffffu, mx, o));
            float s = 0.f;
            if (c0 < nmax) s += __expf(v0 - mx);
            if (c1 < nmax) s += __expf(v1 - mx);
            if (c2 < nmax) s += __expf(v2 - mx);
            if (c3 < nmax) s += __expf(v3 - mx);
#pragma unroll
            for (int o = 16; o > 0; o >>= 1)
                s += __shfl_xor_sync(0xffffffffu, s, o);
            if (lid == 0) {
                g_pmax[(size_t)r_out * NBLK_LG + blockIdx.x] = mx;
                g_psum[(size_t)r_out * NBLK_LG + blockIdx.x] = s;
            }
        }
        __syncthreads();
    }
}

// ================= lse reduce + final output =================
__global__ void lse_reduce() {
    int row = blockIdx.x * 8 + (threadIdx.x >> 5);
    int lid = threadIdx.x & 31;
    float m = -INFINITY, s = 0.f;
    for (int i = lid; i < NBLK_LG; i += 32) {
        float m2 = g_pmax[(size_t)row * NBLK_LG + i];
        float s2 = g_psum[(size_t)row * NBLK_LG + i];
        if (m2 > m) { s = s * __expf(m - m2) + s2; m = m2; }
        else        { s += s2 * __expf(m2 - m); }
    }
#pragma unroll
    for (int o = 16; o > 0; o >>= 1) {
        float m2 = __shfl_xor_sync(0xffffffffu, m, o);
        float s2 = __shfl_xor_sync(0xffffffffu, s, o);
        if (m2 > m) { s = s * __expf(m - m2) + s2; m = m2; }
        else        { s += s2 * __expf(m2 - m); }
    }
    if (lid == 0) g_lse[row] = m + logf(s);
}

#define NOUT ((size_t)BB * TT * VOCAB1)
__global__ void final_out(float* __restrict__ out) {
    size_t g0 = ((size_t)blockIdx.x * blockDim.x + threadIdx.x) * 4;
    if (g0 >= NOUT) return;
    uint32_t row = (uint32_t)(g0 / VOCAB1);
    uint32_t col = (uint32_t)(g0 - (size_t)row * VOCAB1);
    if (col + 3 < VOCAB1 && g0 + 3 < NOUT) {
        const __nv_bfloat16* lp = g_lgb + (size_t)row * VP + col;
        float l = g_lse[row];
        float4 o;
        o.x = __bfloat162float(lp[0]) - l;
        o.y = __bfloat162float(lp[1]) - l;
        o.z = __bfloat162float(lp[2]) - l;
        o.w = __bfloat162float(lp[3]) - l;
        *reinterpret_cast<float4*>(out + g0) = o;
    } else {
        for (int j = 0; j < 4 && g0 + j < NOUT; j++) {
            size_t g = g0 + j;
            uint32_t r = (uint32_t)(g / VOCAB1);
            uint32_t c = (uint32_t)(g - (size_t)r * VOCAB1);
            out[g] = __bfloat162float(g_lgb[(size_t)r * VP + c]) - g_lse[r];
        }
    }
}

// ================= launch =================
extern "C" void kernel_launch(void* const* d_in, const int* in_sizes, int n_in,
                              void* d_out, int out_size) {
    const float* img_feat = (const float*)d_in[0];
    const int*   seq      = (const int*)d_in[1];
    const float* W_img    = (const float*)d_in[2];
    const float* b_img    = (const float*)d_in[3];
    const float* embed    = (const float*)d_in[4];
    const float* W_ih     = (const float*)d_in[5];
    const float* b_ih     = (const float*)d_in[6];
    const float* W_hh     = (const float*)d_in[7];
    const float* b_hh     = (const float*)d_in[8];
    const float* W_logit  = (const float*)d_in[9];
    const float* b_logit  = (const float*)d_in[10];
    float* out = (float*)d_out;

    float *gx, *bias2;
    __nv_bfloat16 *xsb, *wib, *lgb;
    unsigned char *hs8, *wl8;
    cudaGetSymbolAddress((void**)&gx,    g_gx);
    cudaGetSymbolAddress((void**)&bias2, g_bias2);
    cudaGetSymbolAddress((void**)&xsb,   g_xsb);
    cudaGetSymbolAddress((void**)&hs8,   g_hs8);
    cudaGetSymbolAddress((void**)&wl8,   g_wl8);
    cudaGetSymbolAddress((void**)&wib,   g_wib);
    cudaGetSymbolAddress((void**)&lgb,   g_lgb);

    cudaFuncSetAttribute(bmma_gates,     cudaFuncAttributeMaxDynamicSharedMemorySize, LG_DSMEM);
    cudaFuncSetAttribute(bmma_logits8,   cudaFuncAttributeMaxDynamicSharedMemorySize, LG8_DSMEM);
    cudaFuncSetAttribute(lstm_persist64, cudaFuncAttributeMaxDynamicSharedMemorySize, ST_SMEM);

    init_gather<<<1216, 128>>>(seq, embed, b_ih, b_hh);
    conv_all<<<CONV_BLOCKS, 256>>>(W_logit, W_ih, W_hh);
    x0_ksplit<<<dim3(8, 8), 256>>>(img_feat, W_img);
    x0_reduce<<<(BB * DIN) / 256, 256>>>(b_img);
    bmma_gates<<<dim3(16, 10), 256, LG_DSMEM>>>(xsb, wib, bias2, gx);
    lstm_persist64<<<64, 256, ST_SMEM>>>();
    bmma_logits8<<<dim3(NBLK_LG, 10), 256, LG8_DSMEM>>>(hs8, wl8, b_logit, lgb);
    lse_reduce<<<BB * TT / 8, 256>>>();
    final_out<<<(int)((NOUT / 4 + 255) / 256), 256>>>(out);
}